// round 1
// baseline (speedup 1.0000x reference)
#include <cuda_runtime.h>
#include <cstdint>

#define NB 32
#define NT 8
#define NN 512
#define NF 4
#define NH 64
#define NCO 12

// Intermediates (no allocation allowed -> device globals)
__device__ float g_gat[(size_t)NB * NT * NN * NH];   // 8.4M floats, 32MB
__device__ float g_gru[(size_t)NB * NN * NT * NF];   // 524288 floats, 2MB

// Wx row stride in smem (pad 68 to avoid 32-way STS bank conflicts; keeps 16B align)
#define WXS 68

// ---------------------------------------------------------------------------
// Kernel 1: fused GAT (Wx projection + masked softmax + alpha@Wx), one CTA per (b,t)
// ---------------------------------------------------------------------------
__global__ void __launch_bounds__(512, 1)
gat_kernel(const float* __restrict__ x, const float* __restrict__ adj,
           const float* __restrict__ gatW, const float* __restrict__ attS,
           const float* __restrict__ attD, const float* __restrict__ bias)
{
    extern __shared__ float sm[];
    float* sWx  = sm;                 // 512*68
    float* sSrc = sWx + NN * WXS;     // 512
    float* sW   = sSrc + NN;          // 256
    float* sAs  = sW + 256;           // 64
    float* sAd  = sAs + 64;           // 64
    float* sB   = sAd + 64;           // 64
    float* sRed = sB + 64;            // 16

    const int tid = threadIdx.x;
    const int bt  = blockIdx.x;

    if (tid < 256)      sW[tid]        = gatW[tid];
    else if (tid < 320) sAs[tid - 256] = attS[tid - 256];
    else if (tid < 384) sAd[tid - 320] = attD[tid - 320];
    else if (tid < 448) sB[tid - 384]  = bias[tid - 384];
    __syncthreads();

    // ---- Wx for node i = tid; also a_src, a_dst ----
    const float4 xv = *(const float4*)(x + ((size_t)bt * NN + tid) * NF);
    float asrc = 0.f, adst = 0.f;
    {
        float* wrow = sWx + tid * WXS;
        #pragma unroll
        for (int q = 0; q < 16; ++q) {
            float4 o;
            o.x = xv.x * sW[4*q+0] + xv.y * sW[64 + 4*q+0] + xv.z * sW[128 + 4*q+0] + xv.w * sW[192 + 4*q+0];
            o.y = xv.x * sW[4*q+1] + xv.y * sW[64 + 4*q+1] + xv.z * sW[128 + 4*q+1] + xv.w * sW[192 + 4*q+1];
            o.z = xv.x * sW[4*q+2] + xv.y * sW[64 + 4*q+2] + xv.z * sW[128 + 4*q+2] + xv.w * sW[192 + 4*q+2];
            o.w = xv.x * sW[4*q+3] + xv.y * sW[64 + 4*q+3] + xv.z * sW[128 + 4*q+3] + xv.w * sW[192 + 4*q+3];
            *(float4*)(wrow + 4*q) = o;
            asrc += o.x * sAs[4*q+0] + o.y * sAs[4*q+1] + o.z * sAs[4*q+2] + o.w * sAs[4*q+3];
            adst += o.x * sAd[4*q+0] + o.y * sAd[4*q+1] + o.z * sAd[4*q+2] + o.w * sAd[4*q+3];
        }
    }
    sSrc[tid] = asrc;

    // ---- block max of a_src (upper-bound softmax shift; lrelu is monotone) ----
    float v = asrc;
    #pragma unroll
    for (int o = 16; o; o >>= 1) v = fmaxf(v, __shfl_xor_sync(0xffffffffu, v, o));
    if ((tid & 31) == 0) sRed[tid >> 5] = v;
    __syncthreads();
    float smax = sRed[0];
    #pragma unroll
    for (int w = 1; w < 16; ++w) smax = fmaxf(smax, sRed[w]);

    float M = adst + smax;
    M = M > 0.f ? M : 0.2f * M;

    float acc[NH];
    #pragma unroll
    for (int h = 0; h < NH; ++h) acc[h] = 0.f;
    float ssum = 0.f;

    // adj column i: coalesced across threads for fixed j
    const float* adjcol = adj + (size_t)bt * NN * NN + tid;

    #pragma unroll 1
    for (int j0 = 0; j0 < NN; j0 += 4) {
        float a4[4];
        #pragma unroll
        for (int u = 0; u < 4; ++u) a4[u] = __ldg(adjcol + (size_t)(j0 + u) * NN);
        #pragma unroll
        for (int u = 0; u < 4; ++u) {
            const int j = j0 + u;
            float e = adst + sSrc[j];
            e = e > 0.f ? e : 0.2f * e;
            float p = (a4[u] != 0.f || j == tid) ? __expf(e - M) : 0.f;
            ssum += p;
            const float4* wr = (const float4*)(sWx + j * WXS);
            #pragma unroll
            for (int q = 0; q < 16; ++q) {
                float4 w4 = wr[q];            // broadcast LDS, conflict-free
                acc[4*q+0] += p * w4.x;
                acc[4*q+1] += p * w4.y;
                acc[4*q+2] += p * w4.z;
                acc[4*q+3] += p * w4.w;
            }
        }
    }

    const float inv = 1.f / ssum;
    float* op = g_gat + ((size_t)bt * NN + tid) * NH;
    #pragma unroll
    for (int q = 0; q < 16; ++q) {
        float4 o;
        o.x = acc[4*q+0] * inv + sB[4*q+0];
        o.y = acc[4*q+1] * inv + sB[4*q+1];
        o.z = acc[4*q+2] * inv + sB[4*q+2];
        o.w = acc[4*q+3] * inv + sB[4*q+3];
        *(float4*)(op + 4*q) = o;
    }
}

// ---------------------------------------------------------------------------
// Kernel 2: GRU over the raw-view sequences (B*N sequences, T=8, hidden=4)
// seq[m, t, h] = g_gat flat [m*512 + t*64 + h]   (faithful .view, contiguous!)
// ---------------------------------------------------------------------------
__global__ void __launch_bounds__(128)
gru_kernel(const float* __restrict__ Wih, const float* __restrict__ Whh,
           const float* __restrict__ bih, const float* __restrict__ bhh)
{
    __shared__ float sWih[12 * 64];
    __shared__ float sWhh[48];
    __shared__ float sbih[12], sbhh[12];
    const int tid = threadIdx.x;
    for (int k = tid; k < 768; k += 128) sWih[k] = Wih[k];
    if (tid < 48) sWhh[tid] = Whh[tid];
    if (tid < 12) { sbih[tid] = bih[tid]; sbhh[tid] = bhh[tid]; }
    __syncthreads();

    const int m = blockIdx.x * 128 + tid;
    const float4* seq = (const float4*)(g_gat + (size_t)m * (NT * NH));
    float4* op = (float4*)(g_gru + (size_t)m * (NT * NF));

    float h[4] = {0.f, 0.f, 0.f, 0.f};
    for (int t = 0; t < NT; ++t) {
        float gx[12];
        #pragma unroll
        for (int k = 0; k < 12; ++k) gx[k] = sbih[k];
        #pragma unroll
        for (int q = 0; q < 16; ++q) {
            float4 vv = seq[t * 16 + q];
            #pragma unroll
            for (int k = 0; k < 12; ++k) {
                const float* wr = sWih + k * 64 + q * 4;
                gx[k] += vv.x * wr[0] + vv.y * wr[1] + vv.z * wr[2] + vv.w * wr[3];
            }
        }
        float hn[4];
        #pragma unroll
        for (int c = 0; c < 4; ++c) {
            float ghr = sbhh[c]     + h[0]*sWhh[c*4]       + h[1]*sWhh[c*4+1]       + h[2]*sWhh[c*4+2]       + h[3]*sWhh[c*4+3];
            float ghz = sbhh[4 + c] + h[0]*sWhh[(4+c)*4]   + h[1]*sWhh[(4+c)*4+1]   + h[2]*sWhh[(4+c)*4+2]   + h[3]*sWhh[(4+c)*4+3];
            float ghn = sbhh[8 + c] + h[0]*sWhh[(8+c)*4]   + h[1]*sWhh[(8+c)*4+1]   + h[2]*sWhh[(8+c)*4+2]   + h[3]*sWhh[(8+c)*4+3];
            float r  = 1.f / (1.f + __expf(-(gx[c]     + ghr)));
            float z  = 1.f / (1.f + __expf(-(gx[4 + c] + ghz)));
            float nc = tanhf(gx[8 + c] + r * ghn);
            hn[c] = (1.f - z) * nc + z * h[c];
        }
        #pragma unroll
        for (int c = 0; c < 4; ++c) h[c] = hn[c];
        float4 hv; hv.x = h[0]; hv.y = h[1]; hv.z = h[2]; hv.w = h[3];
        op[t] = hv;
    }
}

// ---------------------------------------------------------------------------
// Kernel 3: Conv2d(T=8 -> 12, 3x3, SAME over [N,4]) + Linear(4 -> 2), fused.
// g[b, ci, n, w] = g_gru[((b*512 + n)*8 + ci)*4 + w]
// ---------------------------------------------------------------------------
__global__ void __launch_bounds__(128)
conv_kernel(const float* __restrict__ cW, const float* __restrict__ cB,
            const float* __restrict__ oW, const float* __restrict__ oB,
            float* __restrict__ out)
{
    __shared__ float sW[NCO * NT * 9];   // 864
    __shared__ float sCB[NCO], sOW[8], sOB[2];
    const int tid = threadIdx.x;
    for (int k = tid; k < NCO * NT * 9; k += 128) sW[k] = cW[k];
    if (tid < NCO) sCB[tid] = cB[tid];
    if (tid < 8)   sOW[tid] = oW[tid];
    if (tid < 2)   sOB[tid] = oB[tid];
    __syncthreads();

    const int idx = blockIdx.x * 128 + tid;   // b*512 + n
    const int b = idx >> 9, n = idx & 511;

    float r[3][32];
    const float* base = g_gru + (size_t)b * NN * (NT * NF);
    #pragma unroll
    for (int kh = 0; kh < 3; ++kh) {
        const int nn = n + kh - 1;
        if (nn >= 0 && nn < NN) {
            const float4* rp = (const float4*)(base + (size_t)nn * 32);
            #pragma unroll
            for (int q = 0; q < 8; ++q) {
                float4 vv = rp[q];
                r[kh][q*4+0] = vv.x; r[kh][q*4+1] = vv.y; r[kh][q*4+2] = vv.z; r[kh][q*4+3] = vv.w;
            }
        } else {
            #pragma unroll
            for (int q = 0; q < 32; ++q) r[kh][q] = 0.f;
        }
    }

    float* op = out + ((size_t)b * NCO * NN + n) * 2;
    #pragma unroll 1
    for (int co = 0; co < NCO; ++co) {
        float y0 = sCB[co], y1 = y0, y2 = y0, y3 = y0;
        #pragma unroll
        for (int ci = 0; ci < NT; ++ci) {
            #pragma unroll
            for (int kh = 0; kh < 3; ++kh) {
                const float v0 = r[kh][ci*4+0], v1 = r[kh][ci*4+1];
                const float v2 = r[kh][ci*4+2], v3 = r[kh][ci*4+3];
                const float* wg = &sW[((co * NT + ci) * 3 + kh) * 3];
                const float w0 = wg[0], w1 = wg[1], w2 = wg[2];
                y0 += v0*w1 + v1*w2;
                y1 += v0*w0 + v1*w1 + v2*w2;
                y2 += v1*w0 + v2*w1 + v3*w2;
                y3 += v2*w0 + v3*w1;
            }
        }
        float2 o;
        o.x = sOB[0] + y0*sOW[0] + y1*sOW[1] + y2*sOW[2] + y3*sOW[3];
        o.y = sOB[1] + y0*sOW[4] + y1*sOW[5] + y2*sOW[6] + y3*sOW[7];
        *(float2*)(op + (size_t)co * (NN * 2)) = o;
    }
}

// ---------------------------------------------------------------------------
extern "C" void kernel_launch(void* const* d_in, const int* in_sizes, int n_in,
                              void* d_out, int out_size)
{
    const float* x        = (const float*)d_in[0];
    const float* adj      = (const float*)d_in[1];
    const float* gat_W    = (const float*)d_in[2];
    const float* att_src  = (const float*)d_in[3];
    const float* att_dst  = (const float*)d_in[4];
    const float* gat_bias = (const float*)d_in[5];
    const float* gru_Wih  = (const float*)d_in[6];
    const float* gru_Whh  = (const float*)d_in[7];
    const float* gru_bih  = (const float*)d_in[8];
    const float* gru_bhh  = (const float*)d_in[9];
    const float* conv_W   = (const float*)d_in[10];
    const float* conv_b   = (const float*)d_in[11];
    const float* out_W    = (const float*)d_in[12];
    const float* out_b    = (const float*)d_in[13];
    float* out = (float*)d_out;

    const int smem_bytes = (NN * WXS + NN + 256 + 64 + 64 + 64 + 16) * 4;
    cudaFuncSetAttribute(gat_kernel, cudaFuncAttributeMaxDynamicSharedMemorySize, smem_bytes);

    gat_kernel<<<NB * NT, 512, smem_bytes>>>(x, adj, gat_W, att_src, att_dst, gat_bias);
    gru_kernel<<<(NB * NN) / 128, 128>>>(gru_Wih, gru_Whh, gru_bih, gru_bhh);
    conv_kernel<<<(NB * NN) / 128, 128>>>(conv_W, conv_b, out_W, out_b, out);
}

// round 2
// speedup vs baseline: 1.2056x; 1.2056x over previous
#include <cuda_runtime.h>
#include <cstdint>

#define NB 32
#define NT 8
#define NN 512
#define NF 4
#define NH 64
#define NCO 12

// Intermediates (no allocation allowed -> device globals)
__device__ float g_gat[(size_t)NB * NT * NN * NH];            // 32MB
__device__ float g_gx [(size_t)NT * 12 * (NB * NN)];          // 6MB, layout [t][k][m]
__device__ float g_gru[(size_t)NB * NN * NT * NF];            // 2MB

// Wx row stride in smem: 68 floats = 272B, 16B-aligned
#define WXS 68

__device__ __forceinline__ void ffma2(unsigned long long& d, unsigned long long a, unsigned long long b) {
    asm("fma.rn.f32x2 %0, %1, %2, %0;" : "+l"(d) : "l"(a), "l"(b));
}
__device__ __forceinline__ unsigned long long pack2(float p) {
    unsigned long long r;
    asm("mov.b64 %0, {%1, %1};" : "=l"(r) : "f"(p));
    return r;
}
__device__ __forceinline__ float2 unpack2(unsigned long long v) {
    float2 f;
    asm("mov.b64 {%0, %1}, %2;" : "=f"(f.x), "=f"(f.y) : "l"(v));
    return f;
}

// ---------------------------------------------------------------------------
// Kernel 1: fused GAT. One CTA per (b,t). Thread = (i-pair, h-half):
//   tid>>8 = h-half (32 channels), tid&255 = i-pair -> rows 2*ig, 2*ig+1.
// Mainloop uses packed f32x2 FMA; Wx rows read from smem as double2.
// ---------------------------------------------------------------------------
__global__ void __launch_bounds__(512, 1)
gat_kernel(const float* __restrict__ x, const float* __restrict__ adj,
           const float* __restrict__ gatW, const float* __restrict__ attS,
           const float* __restrict__ attD, const float* __restrict__ bias)
{
    extern __shared__ float sm[];
    float* sWx  = sm;                  // 512*68
    float* sSrc = sWx + NN * WXS;      // 512
    float* sDst = sSrc + NN;           // 512
    float* sW   = sDst + NN;           // 256
    float* sAs  = sW + 256;            // 64
    float* sAd  = sAs + 64;            // 64
    float* sB   = sAd + 64;            // 64
    float* sRed = sB + 64;             // 16

    const int tid = threadIdx.x;
    const int bt  = blockIdx.x;

    if (tid < 256)      sW[tid]        = gatW[tid];
    else if (tid < 320) sAs[tid - 256] = attS[tid - 256];
    else if (tid < 384) sAd[tid - 320] = attD[tid - 320];
    else if (tid < 448) sB[tid - 384]  = bias[tid - 384];
    __syncthreads();

    // ---- Wx for node i = tid; also a_src, a_dst ----
    const float4 xv = *(const float4*)(x + ((size_t)bt * NN + tid) * NF);
    float asrc = 0.f, adst = 0.f;
    {
        float* wrow = sWx + tid * WXS;
        #pragma unroll
        for (int q = 0; q < 16; ++q) {
            float4 o;
            o.x = xv.x * sW[4*q+0] + xv.y * sW[64 + 4*q+0] + xv.z * sW[128 + 4*q+0] + xv.w * sW[192 + 4*q+0];
            o.y = xv.x * sW[4*q+1] + xv.y * sW[64 + 4*q+1] + xv.z * sW[128 + 4*q+1] + xv.w * sW[192 + 4*q+1];
            o.z = xv.x * sW[4*q+2] + xv.y * sW[64 + 4*q+2] + xv.z * sW[128 + 4*q+2] + xv.w * sW[192 + 4*q+2];
            o.w = xv.x * sW[4*q+3] + xv.y * sW[64 + 4*q+3] + xv.z * sW[128 + 4*q+3] + xv.w * sW[192 + 4*q+3];
            *(float4*)(wrow + 4*q) = o;
            asrc += o.x * sAs[4*q+0] + o.y * sAs[4*q+1] + o.z * sAs[4*q+2] + o.w * sAs[4*q+3];
            adst += o.x * sAd[4*q+0] + o.y * sAd[4*q+1] + o.z * sAd[4*q+2] + o.w * sAd[4*q+3];
        }
    }
    sSrc[tid] = asrc;
    sDst[tid] = adst;

    // ---- block max of a_src (valid softmax shift; lrelu monotone) ----
    float v = asrc;
    #pragma unroll
    for (int o = 16; o; o >>= 1) v = fmaxf(v, __shfl_xor_sync(0xffffffffu, v, o));
    if ((tid & 31) == 0) sRed[tid >> 5] = v;
    __syncthreads();
    float smax = sRed[0];
    #pragma unroll
    for (int w = 1; w < 16; ++w) smax = fmaxf(smax, sRed[w]);

    const int half = tid >> 8;          // h-half: 0 or 1
    const int ig   = tid & 255;         // i-pair index
    const int i0   = 2 * ig, i1 = i0 + 1;

    const float adst0 = sDst[i0], adst1 = sDst[i1];
    float M0 = adst0 + smax; M0 = M0 > 0.f ? M0 : 0.2f * M0;
    float M1 = adst1 + smax; M1 = M1 > 0.f ? M1 : 0.2f * M1;

    unsigned long long acc0[16], acc1[16];
    #pragma unroll
    for (int k = 0; k < 16; ++k) { acc0[k] = 0ull; acc1[k] = 0ull; }
    float ssum0 = 0.f, ssum1 = 0.f;

    const float* adjp = adj + (size_t)bt * NN * NN;
    const int hb = half * 32;

    #pragma unroll 1
    for (int j0 = 0; j0 < NN; j0 += 4) {
        float2 a4[4];
        #pragma unroll
        for (int u = 0; u < 4; ++u)
            a4[u] = ((const float2*)(adjp + (size_t)(j0 + u) * NN))[ig];
        #pragma unroll
        for (int u = 0; u < 4; ++u) {
            const int j = j0 + u;
            const float srcj = sSrc[j];
            float e0 = adst0 + srcj; e0 = e0 > 0.f ? e0 : 0.2f * e0;
            float e1 = adst1 + srcj; e1 = e1 > 0.f ? e1 : 0.2f * e1;
            const float p0 = (a4[u].x != 0.f || j == i0) ? __expf(e0 - M0) : 0.f;
            const float p1 = (a4[u].y != 0.f || j == i1) ? __expf(e1 - M1) : 0.f;
            ssum0 += p0; ssum1 += p1;
            const unsigned long long P0 = pack2(p0);
            const unsigned long long P1 = pack2(p1);
            const double2* wr = (const double2*)(sWx + j * WXS + hb);
            #pragma unroll
            for (int q = 0; q < 8; ++q) {
                const double2 w = wr[q];
                const unsigned long long wx = __double_as_longlong(w.x);
                const unsigned long long wy = __double_as_longlong(w.y);
                ffma2(acc0[2*q],     P0, wx);
                ffma2(acc0[2*q + 1], P0, wy);
                ffma2(acc1[2*q],     P1, wx);
                ffma2(acc1[2*q + 1], P1, wy);
            }
        }
    }

    const float inv0 = 1.f / ssum0;
    const float inv1 = 1.f / ssum1;
    float* op0 = g_gat + ((size_t)bt * NN + i0) * NH + hb;
    float* op1 = g_gat + ((size_t)bt * NN + i1) * NH + hb;
    #pragma unroll
    for (int q = 0; q < 8; ++q) {
        const float b0 = sB[hb + 4*q+0], b1 = sB[hb + 4*q+1];
        const float b2 = sB[hb + 4*q+2], b3 = sB[hb + 4*q+3];
        float2 lo0 = unpack2(acc0[2*q]), hi0 = unpack2(acc0[2*q + 1]);
        float2 lo1 = unpack2(acc1[2*q]), hi1 = unpack2(acc1[2*q + 1]);
        float4 o0, o1;
        o0.x = lo0.x * inv0 + b0; o0.y = lo0.y * inv0 + b1;
        o0.z = hi0.x * inv0 + b2; o0.w = hi0.y * inv0 + b3;
        o1.x = lo1.x * inv1 + b0; o1.y = lo1.y * inv1 + b1;
        o1.z = hi1.x * inv1 + b2; o1.w = hi1.y * inv1 + b3;
        *(float4*)(op0 + 4*q) = o0;
        *(float4*)(op1 + 4*q) = o1;
    }
}

// ---------------------------------------------------------------------------
// Kernel 2a: GRU input gates GEMM, fully parallel over (t, m).
// v = t*16384 + m; reads g_gat[m*512 + t*64 .. +64]; writes g_gx[t][k][m]
// (coalesced over m for the recurrence kernel).
// ---------------------------------------------------------------------------
__global__ void __launch_bounds__(256)
gru_gates_kernel(const float* __restrict__ Wih, const float* __restrict__ bih)
{
    __shared__ float sWih[12 * 64];
    __shared__ float sbih[12];
    const int tid = threadIdx.x;
    for (int k = tid; k < 768; k += 256) sWih[k] = Wih[k];
    if (tid < 12) sbih[tid] = bih[tid];
    __syncthreads();

    const int v = blockIdx.x * 256 + tid;
    const int m = v & (NB * NN - 1);
    const int t = v >> 14;

    const float4* src = (const float4*)(g_gat + (size_t)m * (NT * NH) + t * NH);
    float gx[12];
    #pragma unroll
    for (int k = 0; k < 12; ++k) gx[k] = sbih[k];
    #pragma unroll
    for (int q = 0; q < 16; ++q) {
        const float4 vv = src[q];
        #pragma unroll
        for (int k = 0; k < 12; ++k) {
            const float* wr = sWih + k * 64 + q * 4;
            gx[k] += vv.x * wr[0] + vv.y * wr[1] + vv.z * wr[2] + vv.w * wr[3];
        }
    }
    #pragma unroll
    for (int k = 0; k < 12; ++k)
        g_gx[((size_t)t * 12 + k) * (NB * NN) + m] = gx[k];
}

// ---------------------------------------------------------------------------
// Kernel 2b: GRU recurrence (tiny). Thread per sequence m; all g_gx reads
// fully coalesced over m.
// ---------------------------------------------------------------------------
__global__ void __launch_bounds__(256)
gru_rec_kernel(const float* __restrict__ Whh, const float* __restrict__ bhh)
{
    __shared__ float sWhh[48];
    __shared__ float sbhh[12];
    const int tid = threadIdx.x;
    if (tid < 48) sWhh[tid] = Whh[tid];
    if (tid < 12) sbhh[tid] = bhh[tid];
    __syncthreads();

    const int m = blockIdx.x * 256 + tid;
    float h[4] = {0.f, 0.f, 0.f, 0.f};
    float4* op = (float4*)(g_gru + (size_t)m * (NT * NF));

    #pragma unroll
    for (int t = 0; t < NT; ++t) {
        float gx[12];
        #pragma unroll
        for (int k = 0; k < 12; ++k)
            gx[k] = g_gx[((size_t)t * 12 + k) * (NB * NN) + m];
        float hn[4];
        #pragma unroll
        for (int c = 0; c < 4; ++c) {
            float ghr = sbhh[c]     + h[0]*sWhh[c*4]     + h[1]*sWhh[c*4+1]     + h[2]*sWhh[c*4+2]     + h[3]*sWhh[c*4+3];
            float ghz = sbhh[4 + c] + h[0]*sWhh[(4+c)*4] + h[1]*sWhh[(4+c)*4+1] + h[2]*sWhh[(4+c)*4+2] + h[3]*sWhh[(4+c)*4+3];
            float ghn = sbhh[8 + c] + h[0]*sWhh[(8+c)*4] + h[1]*sWhh[(8+c)*4+1] + h[2]*sWhh[(8+c)*4+2] + h[3]*sWhh[(8+c)*4+3];
            float r  = 1.f / (1.f + __expf(-(gx[c]     + ghr)));
            float z  = 1.f / (1.f + __expf(-(gx[4 + c] + ghz)));
            float nc = tanhf(gx[8 + c] + r * ghn);
            hn[c] = (1.f - z) * nc + z * h[c];
        }
        #pragma unroll
        for (int c = 0; c < 4; ++c) h[c] = hn[c];
        float4 hv; hv.x = h[0]; hv.y = h[1]; hv.z = h[2]; hv.w = h[3];
        op[t] = hv;
    }
}

// ---------------------------------------------------------------------------
// Kernel 3: Conv2d(T=8 -> 12, 3x3, SAME over [N,4]) + Linear(4 -> 2), fused.
// ---------------------------------------------------------------------------
__global__ void __launch_bounds__(128)
conv_kernel(const float* __restrict__ cW, const float* __restrict__ cB,
            const float* __restrict__ oW, const float* __restrict__ oB,
            float* __restrict__ out)
{
    __shared__ float sW[NCO * NT * 9];
    __shared__ float sCB[NCO], sOW[8], sOB[2];
    const int tid = threadIdx.x;
    for (int k = tid; k < NCO * NT * 9; k += 128) sW[k] = cW[k];
    if (tid < NCO) sCB[tid] = cB[tid];
    if (tid < 8)   sOW[tid] = oW[tid];
    if (tid < 2)   sOB[tid] = oB[tid];
    __syncthreads();

    const int idx = blockIdx.x * 128 + tid;
    const int b = idx >> 9, n = idx & 511;

    float r[3][32];
    const float* base = g_gru + (size_t)b * NN * (NT * NF);
    #pragma unroll
    for (int kh = 0; kh < 3; ++kh) {
        const int nn = n + kh - 1;
        if (nn >= 0 && nn < NN) {
            const float4* rp = (const float4*)(base + (size_t)nn * 32);
            #pragma unroll
            for (int q = 0; q < 8; ++q) {
                float4 vv = rp[q];
                r[kh][q*4+0] = vv.x; r[kh][q*4+1] = vv.y; r[kh][q*4+2] = vv.z; r[kh][q*4+3] = vv.w;
            }
        } else {
            #pragma unroll
            for (int q = 0; q < 32; ++q) r[kh][q] = 0.f;
        }
    }

    float* op = out + ((size_t)b * NCO * NN + n) * 2;
    #pragma unroll 1
    for (int co = 0; co < NCO; ++co) {
        float y0 = sCB[co], y1 = y0, y2 = y0, y3 = y0;
        #pragma unroll
        for (int ci = 0; ci < NT; ++ci) {
            #pragma unroll
            for (int kh = 0; kh < 3; ++kh) {
                const float v0 = r[kh][ci*4+0], v1 = r[kh][ci*4+1];
                const float v2 = r[kh][ci*4+2], v3 = r[kh][ci*4+3];
                const float* wg = &sW[((co * NT + ci) * 3 + kh) * 3];
                const float w0 = wg[0], w1 = wg[1], w2 = wg[2];
                y0 += v0*w1 + v1*w2;
                y1 += v0*w0 + v1*w1 + v2*w2;
                y2 += v1*w0 + v2*w1 + v3*w2;
                y3 += v2*w0 + v3*w1;
            }
        }
        float2 o;
        o.x = sOB[0] + y0*sOW[0] + y1*sOW[1] + y2*sOW[2] + y3*sOW[3];
        o.y = sOB[1] + y0*sOW[4] + y1*sOW[5] + y2*sOW[6] + y3*sOW[7];
        *(float2*)(op + (size_t)co * (NN * 2)) = o;
    }
}

// ---------------------------------------------------------------------------
extern "C" void kernel_launch(void* const* d_in, const int* in_sizes, int n_in,
                              void* d_out, int out_size)
{
    const float* x        = (const float*)d_in[0];
    const float* adj      = (const float*)d_in[1];
    const float* gat_W    = (const float*)d_in[2];
    const float* att_src  = (const float*)d_in[3];
    const float* att_dst  = (const float*)d_in[4];
    const float* gat_bias = (const float*)d_in[5];
    const float* gru_Wih  = (const float*)d_in[6];
    const float* gru_Whh  = (const float*)d_in[7];
    const float* gru_bih  = (const float*)d_in[8];
    const float* gru_bhh  = (const float*)d_in[9];
    const float* conv_W   = (const float*)d_in[10];
    const float* conv_b   = (const float*)d_in[11];
    const float* out_W    = (const float*)d_in[12];
    const float* out_b    = (const float*)d_in[13];
    float* out = (float*)d_out;

    const int smem_bytes = (NN * WXS + NN + NN + 256 + 64 + 64 + 64 + 16) * 4;
    cudaFuncSetAttribute(gat_kernel, cudaFuncAttributeMaxDynamicSharedMemorySize, smem_bytes);

    gat_kernel<<<NB * NT, 512, smem_bytes>>>(x, adj, gat_W, att_src, att_dst, gat_bias);
    gru_gates_kernel<<<(NB * NN * NT) / 256, 256>>>(gru_Wih, gru_bih);
    gru_rec_kernel<<<(NB * NN) / 256, 256>>>(gru_Whh, gru_bhh);
    conv_kernel<<<(NB * NN) / 128, 128>>>(conv_W, conv_b, out_W, out_b, out);
}

// round 5
// speedup vs baseline: 3.8741x; 3.2134x over previous
#include <cuda_runtime.h>
#include <cstdint>

#define NB 32
#define NT 8
#define NN 512
#define NF 4
#define NH 64
#define NCO 12

// Intermediates (device globals; no allocation allowed)
__device__ float4 g_acc[(size_t)NB * NT * NN];        // unnormalized (alpha @ x), 2.1MB
__device__ float  g_inv[(size_t)NB * NT * NN];        // 1/softmax-sum, 0.5MB
__device__ float  g_gru[(size_t)NB * NN * NT * NF];   // 2MB
// Precomputed small tensors
__device__ __align__(16) float g_wsd[8];              // ws[4] = W@attS, wd[4] = W@attD
__device__ float g_C[48];                             // C[f][k] = sum_h W[f,h]*Wih[k,h]
__device__ float g_d[12];                             // d[k] = Wih@bias + bih

__device__ __forceinline__ float lrelu(float v) { return v > 0.f ? v : 0.2f * v; }

// ---------------------------------------------------------------------------
// Kernel 0: tiny prep — fold W/att/Wih/bias into ws, wd, C, d.
// ---------------------------------------------------------------------------
__global__ void __launch_bounds__(128)
prep_kernel(const float* __restrict__ gatW, const float* __restrict__ attS,
            const float* __restrict__ attD, const float* __restrict__ bias,
            const float* __restrict__ Wih, const float* __restrict__ bih)
{
    const int tid = threadIdx.x;
    if (tid < 48) {
        const int f = tid / 12, k = tid % 12;
        float s = 0.f;
        for (int h = 0; h < NH; ++h) s += gatW[f * NH + h] * Wih[k * NH + h];
        g_C[f * 12 + k] = s;
    } else if (tid < 52) {
        const int f = tid - 48;
        float s = 0.f;
        for (int h = 0; h < NH; ++h) s += gatW[f * NH + h] * attS[h];
        g_wsd[f] = s;
    } else if (tid < 56) {
        const int f = tid - 52;
        float s = 0.f;
        for (int h = 0; h < NH; ++h) s += gatW[f * NH + h] * attD[h];
        g_wsd[4 + f] = s;
    } else if (tid < 68) {
        const int k = tid - 56;
        float s = bih[k];
        for (int h = 0; h < NH; ++h) s += Wih[k * NH + h] * bias[h];
        g_d[k] = s;
    }
}

// ---------------------------------------------------------------------------
// Kernel 1: fused GAT, restructured as (alpha @ x). One CTA per (bt, half);
// thread owns target node i. Streams adj exactly once (coalesced columns).
// ---------------------------------------------------------------------------
__global__ void __launch_bounds__(256)
gat_kernel(const float* __restrict__ x, const float* __restrict__ adj)
{
    __shared__ float4 sX[NN];
    __shared__ float  sAsrc[NN];
    __shared__ float  sRed[8];

    const int tid  = threadIdx.x;
    const int bt   = blockIdx.x >> 1;
    const int half = blockIdx.x & 1;

    const float4* xg = (const float4*)(x + (size_t)bt * NN * NF);
    sX[tid]       = xg[tid];
    sX[tid + 256] = xg[tid + 256];
    __syncthreads();

    const float4 wsv = *(const float4*)(g_wsd);
    const float4 wdv = *(const float4*)(g_wsd + 4);

    #pragma unroll
    for (int r = 0; r < 2; ++r) {
        const int i = tid + r * 256;
        const float4 xv = sX[i];
        sAsrc[i] = xv.x * wsv.x + xv.y * wsv.y + xv.z * wsv.z + xv.w * wsv.w;
    }
    const int ig = half * 256 + tid;
    const float4 xi = sX[ig];
    const float adst = xi.x * wdv.x + xi.y * wdv.y + xi.z * wdv.z + xi.w * wdv.w;
    __syncthreads();

    // block max of a_src (valid softmax shift; lrelu monotone)
    float v = fmaxf(sAsrc[tid], sAsrc[tid + 256]);
    #pragma unroll
    for (int o = 16; o; o >>= 1) v = fmaxf(v, __shfl_xor_sync(0xffffffffu, v, o));
    if ((tid & 31) == 0) sRed[tid >> 5] = v;
    __syncthreads();
    float smax = sRed[0];
    #pragma unroll
    for (int w = 1; w < 8; ++w) smax = fmaxf(smax, sRed[w]);

    const float M = lrelu(adst + smax);

    float ax = 0.f, ay = 0.f, az = 0.f, aw = 0.f, ssum = 0.f;
    const float* ap = adj + (size_t)bt * NN * NN + ig;

    #pragma unroll 1
    for (int j0 = 0; j0 < NN; j0 += 8) {
        float a[8];
        #pragma unroll
        for (int u = 0; u < 8; ++u)
            a[u] = __ldg(ap + (size_t)(j0 + u) * NN);
        #pragma unroll
        for (int u = 0; u < 8; ++u) {
            const int j = j0 + u;
            const float e = lrelu(adst + sAsrc[j]);
            const float p = (a[u] != 0.f || j == ig) ? __expf(e - M) : 0.f;
            ssum += p;
            const float4 xj = sX[j];
            ax += p * xj.x; ay += p * xj.y; az += p * xj.z; aw += p * xj.w;
        }
    }

    const size_t o = (size_t)bt * NN + ig;
    float4 av; av.x = ax; av.y = ay; av.z = az; av.w = aw;
    g_acc[o] = av;
    g_inv[o] = 1.f / ssum;
}

// ---------------------------------------------------------------------------
// Kernel 2: GRU gates (folded through C, d) + recurrence, fully fused.
// seq element (m, t) maps to gat flat index -> (bt', n') with
//   b = m>>9, t' = (m>>6)&7, n' = (m&63)*8 + t  (raw .view faithfulness).
// The 8 t-reads per thread are CONSECUTIVE float4s.
// ---------------------------------------------------------------------------
__global__ void __launch_bounds__(256)
gru_rec_kernel(const float* __restrict__ Whh, const float* __restrict__ bhh)
{
    __shared__ float sC[48], sd[12], sWhh[48], sbhh[12];
    const int tid = threadIdx.x;
    if (tid < 48) { sC[tid] = g_C[tid]; sWhh[tid] = Whh[tid]; }
    if (tid < 12) { sd[tid] = g_d[tid]; sbhh[tid] = bhh[tid]; }
    __syncthreads();

    const int m = blockIdx.x * 256 + tid;
    const int base = ((m >> 9) * 8 + ((m >> 6) & 7)) * NN + (m & 63) * 8;

    float h[4] = {0.f, 0.f, 0.f, 0.f};
    float4* op = (float4*)(g_gru + (size_t)m * (NT * NF));

    #pragma unroll
    for (int t = 0; t < NT; ++t) {
        const float4 a = g_acc[base + t];
        const float inv = g_inv[base + t];
        float gx[12];
        #pragma unroll
        for (int k = 0; k < 12; ++k)
            gx[k] = inv * (a.x * sC[k] + a.y * sC[12 + k] + a.z * sC[24 + k] + a.w * sC[36 + k]) + sd[k];

        float hn[4];
        #pragma unroll
        for (int c = 0; c < 4; ++c) {
            float ghr = sbhh[c]     + h[0]*sWhh[c*4]     + h[1]*sWhh[c*4+1]     + h[2]*sWhh[c*4+2]     + h[3]*sWhh[c*4+3];
            float ghz = sbhh[4 + c] + h[0]*sWhh[(4+c)*4] + h[1]*sWhh[(4+c)*4+1] + h[2]*sWhh[(4+c)*4+2] + h[3]*sWhh[(4+c)*4+3];
            float ghn = sbhh[8 + c] + h[0]*sWhh[(8+c)*4] + h[1]*sWhh[(8+c)*4+1] + h[2]*sWhh[(8+c)*4+2] + h[3]*sWhh[(8+c)*4+3];
            float r  = 1.f / (1.f + __expf(-(gx[c]     + ghr)));
            float z  = 1.f / (1.f + __expf(-(gx[4 + c] + ghz)));
            float nc = tanhf(gx[8 + c] + r * ghn);
            hn[c] = (1.f - z) * nc + z * h[c];
        }
        #pragma unroll
        for (int c = 0; c < 4; ++c) h[c] = hn[c];
        float4 hv; hv.x = h[0]; hv.y = h[1]; hv.z = h[2]; hv.w = h[3];
        op[t] = hv;
    }
}

// ---------------------------------------------------------------------------
// Kernel 3: Conv2d(8->12, 3x3 SAME over [N,4]) + Linear(4->2), split over co
// pairs for occupancy (6 groups x 2 channels).
// ---------------------------------------------------------------------------
__global__ void __launch_bounds__(128)
conv_kernel(const float* __restrict__ cW, const float* __restrict__ cB,
            const float* __restrict__ oW, const float* __restrict__ oB,
            float* __restrict__ out)
{
    __shared__ float sW[NCO * NT * 9];
    __shared__ float sCB[NCO], sOW[8], sOB[2];
    const int tid = threadIdx.x;
    for (int k = tid; k < NCO * NT * 9; k += 128) sW[k] = cW[k];
    if (tid < NCO) sCB[tid] = cB[tid];
    if (tid < 8)   sOW[tid] = oW[tid];
    if (tid < 2)   sOB[tid] = oB[tid];
    __syncthreads();

    const int cog = blockIdx.x >> 7;          // 0..5
    const int bn  = blockIdx.x & 127;
    const int idx = bn * 128 + tid;
    const int b = idx >> 9, n = idx & 511;

    float r[3][32];
    const float* base = g_gru + (size_t)b * NN * (NT * NF);
    #pragma unroll
    for (int kh = 0; kh < 3; ++kh) {
        const int nn = n + kh - 1;
        if (nn >= 0 && nn < NN) {
            const float4* rp = (const float4*)(base + (size_t)nn * 32);
            #pragma unroll
            for (int q = 0; q < 8; ++q) {
                float4 vv = rp[q];
                r[kh][q*4+0] = vv.x; r[kh][q*4+1] = vv.y; r[kh][q*4+2] = vv.z; r[kh][q*4+3] = vv.w;
            }
        } else {
            #pragma unroll
            for (int q = 0; q < 32; ++q) r[kh][q] = 0.f;
        }
    }

    float* op = out + ((size_t)b * NCO * NN + n) * 2;
    #pragma unroll
    for (int cc = 0; cc < 2; ++cc) {
        const int co = cog * 2 + cc;
        float y0 = sCB[co], y1 = y0, y2 = y0, y3 = y0;
        #pragma unroll
        for (int ci = 0; ci < NT; ++ci) {
            #pragma unroll
            for (int kh = 0; kh < 3; ++kh) {
                const float v0 = r[kh][ci*4+0], v1 = r[kh][ci*4+1];
                const float v2 = r[kh][ci*4+2], v3 = r[kh][ci*4+3];
                const float* wg = &sW[((co * NT + ci) * 3 + kh) * 3];
                const float w0 = wg[0], w1 = wg[1], w2 = wg[2];
                y0 += v0*w1 + v1*w2;
                y1 += v0*w0 + v1*w1 + v2*w2;
                y2 += v1*w0 + v2*w1 + v3*w2;
                y3 += v2*w0 + v3*w1;
            }
        }
        float2 o;
        o.x = sOB[0] + y0*sOW[0] + y1*sOW[1] + y2*sOW[2] + y3*sOW[3];
        o.y = sOB[1] + y0*sOW[4] + y1*sOW[5] + y2*sOW[6] + y3*sOW[7];
        *(float2*)(op + (size_t)co * (NN * 2)) = o;
    }
}

// ---------------------------------------------------------------------------
extern "C" void kernel_launch(void* const* d_in, const int* in_sizes, int n_in,
                              void* d_out, int out_size)
{
    const float* x        = (const float*)d_in[0];
    const float* adj      = (const float*)d_in[1];
    const float* gat_W    = (const float*)d_in[2];
    const float* att_src  = (const float*)d_in[3];
    const float* att_dst  = (const float*)d_in[4];
    const float* gat_bias = (const float*)d_in[5];
    const float* gru_Wih  = (const float*)d_in[6];
    const float* gru_Whh  = (const float*)d_in[7];
    const float* gru_bih  = (const float*)d_in[8];
    const float* gru_bhh  = (const float*)d_in[9];
    const float* conv_W   = (const float*)d_in[10];
    const float* conv_b   = (const float*)d_in[11];
    const float* out_W    = (const float*)d_in[12];
    const float* out_b    = (const float*)d_in[13];
    float* out = (float*)d_out;

    prep_kernel<<<1, 128>>>(gat_W, att_src, att_dst, gat_bias, gru_Wih, gru_bih);
    gat_kernel<<<NB * NT * 2, 256>>>(x, adj);
    gru_rec_kernel<<<(NB * NN) / 256, 256>>>(gru_Whh, gru_bhh);
    conv_kernel<<<6 * 128, 128>>>(conv_W, conv_b, out_W, out_b, out);
}

// round 7
// speedup vs baseline: 5.7543x; 1.4853x over previous
#include <cuda_runtime.h>
#include <cstdint>

#define NB 32
#define NT 8
#define NN 512
#define NF 4
#define NH 64
#define NCO 12
#define L2E 1.442695040888963f

// Intermediates (device globals; no allocation allowed)
__device__ float4 g_acc[(size_t)NB * NT * NN];        // unnormalized (alpha @ x)
__device__ float  g_inv[(size_t)NB * NT * NN];        // 1/softmax-sum
__device__ float  g_gru[(size_t)NB * NN * NT * NF];   // 2MB
// Precomputed small tensors
__device__ __align__(16) float g_wsd[8];              // ws = W@attS, wd = W@attD
__device__ float g_C[48];                             // C[f][k] = sum_h W[f,h]*Wih[k,h]
__device__ float g_d[12];                             // d[k] = Wih@bias + bih

__device__ __forceinline__ float ex2f(float v) {
    float r; asm("ex2.approx.f32 %0, %1;" : "=f"(r) : "f"(v)); return r;
}

// ---------------------------------------------------------------------------
// Kernel 0: fold W/att/Wih/bias into ws, wd, C, d.
// ---------------------------------------------------------------------------
__global__ void __launch_bounds__(128)
prep_kernel(const float* __restrict__ gatW, const float* __restrict__ attS,
            const float* __restrict__ attD, const float* __restrict__ bias,
            const float* __restrict__ Wih, const float* __restrict__ bih)
{
    const int tid = threadIdx.x;
    if (tid < 48) {
        const int f = tid / 12, k = tid % 12;
        float s = 0.f;
        for (int h = 0; h < NH; ++h) s += gatW[f * NH + h] * Wih[k * NH + h];
        g_C[f * 12 + k] = s;
    } else if (tid < 52) {
        const int f = tid - 48;
        float s = 0.f;
        for (int h = 0; h < NH; ++h) s += gatW[f * NH + h] * attS[h];
        g_wsd[f] = s;
    } else if (tid < 56) {
        const int f = tid - 52;
        float s = 0.f;
        for (int h = 0; h < NH; ++h) s += gatW[f * NH + h] * attD[h];
        g_wsd[4 + f] = s;
    } else if (tid < 68) {
        const int k = tid - 56;
        float s = bih[k];
        for (int h = 0; h < NH; ++h) s += Wih[k * NH + h] * bias[h];
        g_d[k] = s;
    }
}

// ---------------------------------------------------------------------------
// Kernel 1: fused GAT as (alpha @ x). One CTA per (b,t); 512 threads.
// Thread = (j-split s = tid>>7, i-quad iq = tid&127). LDG.128 over i,
// 4-way j-split, smem partial reduction. Diagonal handled by post-fixup.
// ---------------------------------------------------------------------------
__global__ void __launch_bounds__(512, 2)
gat_kernel(const float* __restrict__ x, const float* __restrict__ adj)
{
    extern __shared__ char smraw[];
    float4* sX    = (float4*)smraw;                       // 512 * 16B
    float*  sAsrc = (float*)(smraw + 8192);               // 512
    float*  sRed  = (float*)(smraw + 8192 + 2048);        // 16
    float*  sPart = (float*)(smraw + 8192 + 2048 + 64);   // 4*128*20

    const int tid = threadIdx.x;
    const int bt  = blockIdx.x;

    const float4* xg = (const float4*)(x + (size_t)bt * NN * NF);
    sX[tid] = xg[tid];
    __syncthreads();

    const float4 wsv = *(const float4*)(g_wsd);
    const float4 wdv = *(const float4*)(g_wsd + 4);

    {
        const float4 xv = sX[tid];
        sAsrc[tid] = xv.x * wsv.x + xv.y * wsv.y + xv.z * wsv.z + xv.w * wsv.w;
    }
    __syncthreads();

    // block max of a_src (valid softmax shift; lrelu monotone)
    float v = sAsrc[tid];
    #pragma unroll
    for (int o = 16; o; o >>= 1) v = fmaxf(v, __shfl_xor_sync(0xffffffffu, v, o));
    if ((tid & 31) == 0) sRed[tid >> 5] = v;
    __syncthreads();
    float smax = sRed[0];
    #pragma unroll
    for (int w = 1; w < 16; ++w) smax = fmaxf(smax, sRed[w]);

    const int s  = tid >> 7;        // j-split 0..3
    const int iq = tid & 127;       // i-quad
    const int i0 = iq * 4;

    float adst[4], Mlog[4];
    #pragma unroll
    for (int ii = 0; ii < 4; ++ii) {
        const float4 xi = sX[i0 + ii];
        const float ad = xi.x * wdv.x + xi.y * wdv.y + xi.z * wdv.z + xi.w * wdv.w;
        adst[ii] = ad;
        const float t = ad + smax;
        Mlog[ii] = fmaxf(t, 0.2f * t) * L2E;
    }

    float ssum[4] = {0.f, 0.f, 0.f, 0.f};
    float ax[4] = {0.f, 0.f, 0.f, 0.f};
    float ay[4] = {0.f, 0.f, 0.f, 0.f};
    float az[4] = {0.f, 0.f, 0.f, 0.f};
    float aw[4] = {0.f, 0.f, 0.f, 0.f};

    const float* ap = adj + (size_t)bt * NN * NN + i0;
    const int jbeg = s * 128, jend = jbeg + 128;

    #pragma unroll 1
    for (int j = jbeg; j < jend; j += 2) {
        const float4 a0 = __ldg((const float4*)(ap + (size_t)j * NN));
        const float4 a1 = __ldg((const float4*)(ap + (size_t)(j + 1) * NN));
        #pragma unroll
        for (int u = 0; u < 2; ++u) {
            const float4 a = u ? a1 : a0;
            const float asj = sAsrc[j + u];
            const float4 xj = sX[j + u];
            const float am[4] = {a.x, a.y, a.z, a.w};
            #pragma unroll
            for (int ii = 0; ii < 4; ++ii) {
                const float t = adst[ii] + asj;
                const float e = fmaxf(t, 0.2f * t);
                float p = ex2f(fmaf(e, L2E, -Mlog[ii]));
                p = (am[ii] != 0.f) ? p : 0.f;
                ssum[ii] += p;
                ax[ii] += p * xj.x; ay[ii] += p * xj.y;
                az[ii] += p * xj.z; aw[ii] += p * xj.w;
            }
        }
    }

    // diagonal fixup: my split contains my quad's diagonal iff (iq>>5)==s
    if ((iq >> 5) == s) {
        #pragma unroll
        for (int ii = 0; ii < 4; ++ii) {
            const int i = i0 + ii;
            const float aii = __ldg(ap + (size_t)i * NN + ii);
            if (aii == 0.f) {
                const float t = adst[ii] + sAsrc[i];
                const float e = fmaxf(t, 0.2f * t);
                const float p = ex2f(fmaf(e, L2E, -Mlog[ii]));
                const float4 xi = sX[i];
                ssum[ii] += p;
                ax[ii] += p * xi.x; ay[ii] += p * xi.y;
                az[ii] += p * xi.z; aw[ii] += p * xi.w;
            }
        }
    }

    float* pp = sPart + (size_t)(s * 128 + iq) * 20;
    #pragma unroll
    for (int ii = 0; ii < 4; ++ii) {
        pp[ii * 5 + 0] = ax[ii]; pp[ii * 5 + 1] = ay[ii];
        pp[ii * 5 + 2] = az[ii]; pp[ii * 5 + 3] = aw[ii];
        pp[ii * 5 + 4] = ssum[ii];
    }
    __syncthreads();

    // final reduce over splits: thread tid owns target i = tid
    const int q2 = tid >> 2, i2 = tid & 3;
    float vx = 0.f, vy = 0.f, vz = 0.f, vw = 0.f, sv = 0.f;
    #pragma unroll
    for (int s2 = 0; s2 < 4; ++s2) {
        const float* p2 = sPart + (size_t)(s2 * 128 + q2) * 20 + i2 * 5;
        vx += p2[0]; vy += p2[1]; vz += p2[2]; vw += p2[3]; sv += p2[4];
    }
    const size_t o = (size_t)bt * NN + tid;
    float4 av; av.x = vx; av.y = vy; av.z = vz; av.w = vw;
    g_acc[o] = av;
    g_inv[o] = 1.f / sv;
}

// ---------------------------------------------------------------------------
// Kernel 2: GRU gates (folded through C, d) + recurrence, fused.
//   b = m>>9, t' = (m>>6)&7, n' = (m&63)*8 + t  (raw .view faithfulness)
// ---------------------------------------------------------------------------
__global__ void __launch_bounds__(256)
gru_rec_kernel(const float* __restrict__ Whh, const float* __restrict__ bhh)
{
    __shared__ float sC[48], sd[12], sWhh[48], sbhh[12];
    const int tid = threadIdx.x;
    if (tid < 48) { sC[tid] = g_C[tid]; sWhh[tid] = Whh[tid]; }
    if (tid < 12) { sd[tid] = g_d[tid]; sbhh[tid] = bhh[tid]; }
    __syncthreads();

    const int m = blockIdx.x * 256 + tid;
    const int base = ((m >> 9) * 8 + ((m >> 6) & 7)) * NN + (m & 63) * 8;

    float h[4] = {0.f, 0.f, 0.f, 0.f};
    float4* op = (float4*)(g_gru + (size_t)m * (NT * NF));

    #pragma unroll
    for (int t = 0; t < NT; ++t) {
        const float4 a = g_acc[base + t];
        const float inv = g_inv[base + t];
        float gx[12];
        #pragma unroll
        for (int k = 0; k < 12; ++k)
            gx[k] = inv * (a.x * sC[k] + a.y * sC[12 + k] + a.z * sC[24 + k] + a.w * sC[36 + k]) + sd[k];

        float hn[4];
        #pragma unroll
        for (int c = 0; c < 4; ++c) {
            float ghr = sbhh[c]     + h[0]*sWhh[c*4]     + h[1]*sWhh[c*4+1]     + h[2]*sWhh[c*4+2]     + h[3]*sWhh[c*4+3];
            float ghz = sbhh[4 + c] + h[0]*sWhh[(4+c)*4] + h[1]*sWhh[(4+c)*4+1] + h[2]*sWhh[(4+c)*4+2] + h[3]*sWhh[(4+c)*4+3];
            float ghn = sbhh[8 + c] + h[0]*sWhh[(8+c)*4] + h[1]*sWhh[(8+c)*4+1] + h[2]*sWhh[(8+c)*4+2] + h[3]*sWhh[(8+c)*4+3];
            float r  = 1.f / (1.f + __expf(-(gx[c]     + ghr)));
            float z  = 1.f / (1.f + __expf(-(gx[4 + c] + ghz)));
            float nc = tanhf(gx[8 + c] + r * ghn);
            hn[c] = (1.f - z) * nc + z * h[c];
        }
        #pragma unroll
        for (int c = 0; c < 4; ++c) h[c] = hn[c];
        float4 hv; hv.x = h[0]; hv.y = h[1]; hv.z = h[2]; hv.w = h[3];
        op[t] = hv;
    }
}

// ---------------------------------------------------------------------------
// Kernel 3: Conv2d(8->12, 3x3 SAME over [N,4]) + Linear(4->2).
// Block = (b, n-group of 128, co-group of 6). smem tile 130 rows (pad-9
// float4 stride => conflict-free LDS.128), weights float4-packed.
// ---------------------------------------------------------------------------
__global__ void __launch_bounds__(128)
conv_kernel(const float* __restrict__ cW, const float* __restrict__ cB,
            const float* __restrict__ oW, const float* __restrict__ oB,
            float* __restrict__ out)
{
    __shared__ float4 sG[130 * 9];
    __shared__ float4 sW4[144];          // [(ci*3+kh)*6 + cc] = {w0,w1,w2,0}
    __shared__ float sCB[6], sOW[8], sOB[2];

    const int tid = threadIdx.x;
    const int cog = blockIdx.x >> 7;               // 0..1  (co 6*cog .. +5)
    const int b   = (blockIdx.x >> 2) & 31;
    const int n0  = (blockIdx.x & 3) * 128;

    for (int k = tid; k < 144; k += 128) {
        const int cc = k % 6, r = k / 6, kh = r % 3, ci = r / 3;
        const int co = cog * 6 + cc;
        const float* wp = cW + (((size_t)co * NT + ci) * 3 + kh) * 3;
        float4 w; w.x = wp[0]; w.y = wp[1]; w.z = wp[2]; w.w = 0.f;
        sW4[k] = w;
    }
    if (tid < 6) sCB[tid] = cB[cog * 6 + tid];
    if (tid < 8) sOW[tid] = oW[tid];
    if (tid < 2) sOB[tid] = oB[tid];

    const float4* gp = (const float4*)(g_gru + (size_t)b * NN * 32);
    for (int k = tid; k < 1040; k += 128) {
        const int row = k >> 3, q = k & 7;
        const int nn = n0 + row - 1;
        float4 val = {0.f, 0.f, 0.f, 0.f};
        if (nn >= 0 && nn < NN) val = gp[nn * 8 + q];
        sG[row * 9 + q] = val;
    }
    __syncthreads();

    float y[6][4];
    #pragma unroll
    for (int cc = 0; cc < 6; ++cc) {
        const float cb = sCB[cc];
        y[cc][0] = cb; y[cc][1] = cb; y[cc][2] = cb; y[cc][3] = cb;
    }

    #pragma unroll
    for (int ci = 0; ci < NT; ++ci) {
        #pragma unroll
        for (int kh = 0; kh < 3; ++kh) {
            const float4 vv = sG[(tid + kh) * 9 + ci];
            #pragma unroll
            for (int cc = 0; cc < 6; ++cc) {
                const float4 w4 = sW4[(ci * 3 + kh) * 6 + cc];
                y[cc][0] += vv.x * w4.y + vv.y * w4.z;
                y[cc][1] += vv.x * w4.x + vv.y * w4.y + vv.z * w4.z;
                y[cc][2] += vv.y * w4.x + vv.z * w4.y + vv.w * w4.z;
                y[cc][3] += vv.z * w4.x + vv.w * w4.y;
            }
        }
    }

    const int n = n0 + tid;
    float* op = out + ((size_t)b * NCO * NN + n) * 2 + (size_t)(cog * 6) * (NN * 2);
    #pragma unroll
    for (int cc = 0; cc < 6; ++cc) {
        float2 o;
        o.x = sOB[0] + y[cc][0]*sOW[0] + y[cc][1]*sOW[1] + y[cc][2]*sOW[2] + y[cc][3]*sOW[3];
        o.y = sOB[1] + y[cc][0]*sOW[4] + y[cc][1]*sOW[5] + y[cc][2]*sOW[6] + y[cc][3]*sOW[7];
        *(float2*)(op + (size_t)cc * (NN * 2)) = o;
    }
}

// ---------------------------------------------------------------------------
extern "C" void kernel_launch(void* const* d_in, const int* in_sizes, int n_in,
                              void* d_out, int out_size)
{
    const float* x        = (const float*)d_in[0];
    const float* adj      = (const float*)d_in[1];
    const float* gat_W    = (const float*)d_in[2];
    const float* att_src  = (const float*)d_in[3];
    const float* att_dst  = (const float*)d_in[4];
    const float* gat_bias = (const float*)d_in[5];
    const float* gru_Wih  = (const float*)d_in[6];
    const float* gru_Whh  = (const float*)d_in[7];
    const float* gru_bih  = (const float*)d_in[8];
    const float* gru_bhh  = (const float*)d_in[9];
    const float* conv_W   = (const float*)d_in[10];
    const float* conv_b   = (const float*)d_in[11];
    const float* out_W    = (const float*)d_in[12];
    const float* out_b    = (const float*)d_in[13];
    float* out = (float*)d_out;

    const int gat_smem = 8192 + 2048 + 64 + 4 * 128 * 20 * 4;   // 51264 B
    cudaFuncSetAttribute(gat_kernel, cudaFuncAttributeMaxDynamicSharedMemorySize, gat_smem);

    prep_kernel<<<1, 128>>>(gat_W, att_src, att_dst, gat_bias, gru_Wih, gru_bih);
    gat_kernel<<<NB * NT, 512, gat_smem>>>(x, adj);
    gru_rec_kernel<<<(NB * NN) / 256, 256>>>(gru_Whh, gru_bhh);
    conv_kernel<<<2 * 128, 128>>>(conv_W, conv_b, out_W, out_b, out);
}

// round 8
// speedup vs baseline: 6.8973x; 1.1986x over previous
#include <cuda_runtime.h>
#include <cstdint>

#define NB 32
#define NT 8
#define NN 512
#define NF 4
#define NH 64
#define NCO 12
#define L2E 1.442695040888963f
#define C02 (0.2f * 1.442695040888963f)

// Intermediates (device globals; no allocation allowed)
__device__ __align__(16) float4 g_acc[(size_t)NB * NT * NN];   // unnormalized (alpha @ x)
__device__ __align__(16) float  g_inv[(size_t)NB * NT * NN];   // 1/softmax-sum
__device__ __align__(16) float  g_gru[(size_t)NB * NN * NT * NF];

__device__ __forceinline__ float ex2f(float v) {
    float r; asm("ex2.approx.f32 %0, %1;" : "=f"(r) : "f"(v)); return r;
}
__device__ __forceinline__ float rcpf(float v) {
    float r; asm("rcp.approx.f32 %0, %1;" : "=f"(r) : "f"(v)); return r;
}
__device__ __forceinline__ float sigmf(float x) {           // NaN-safe at extremes
    return rcpf(1.f + ex2f(-L2E * x));
}
__device__ __forceinline__ float tanhfast(float x) {
    const float E = ex2f(fminf(2.f * L2E * x, 80.f));
    return (E - 1.f) * rcpf(E + 1.f);
}

// ---------------------------------------------------------------------------
// Kernel 1: fused GAT as (alpha @ x). One CTA per (b,t); 512 threads.
// Thread = (j-split s = tid>>7, i-quad iq = tid&127). 4x LDG.128 batched,
// pre-scaled exp pipeline, smem partial reduction, diagonal post-fixup.
// ---------------------------------------------------------------------------
__global__ void __launch_bounds__(512, 2)
gat_kernel(const float* __restrict__ x, const float* __restrict__ adj,
           const float* __restrict__ gatW, const float* __restrict__ attS,
           const float* __restrict__ attD)
{
    extern __shared__ char smraw[];
    float4* sX   = (float4*)smraw;                        // 512 * 16B
    float2* sS2  = (float2*)(smraw + 8192);               // 512 * 8B
    float*  sRed = (float*)(smraw + 8192 + 4096);         // 16
    float*  sWsd = (float*)(smraw + 8192 + 4096 + 64);    // 8
    float*  sPart= (float*)(smraw + 8192 + 4096 + 64 + 32); // 4*128*20

    const int tid = threadIdx.x;
    const int bt  = blockIdx.x;

    const float4* xg = (const float4*)(x + (size_t)bt * NN * NF);
    sX[tid] = xg[tid];
    if (tid < 8) {
        const int f = tid & 3;
        const float* wrow = gatW + f * NH;
        const float* av   = (tid < 4) ? attS : attD;
        float s = 0.f;
        for (int h = 0; h < NH; ++h) s += wrow[h] * av[h];
        sWsd[tid] = s;
    }
    __syncthreads();

    const float4 wsv = *(const float4*)(sWsd);
    const float4 wdv = *(const float4*)(sWsd + 4);

    float asrc;
    {
        const float4 xv = sX[tid];
        asrc = xv.x * wsv.x + xv.y * wsv.y + xv.z * wsv.z + xv.w * wsv.w;
        float2 ss; ss.x = asrc * L2E; ss.y = asrc * C02;
        sS2[tid] = ss;
    }
    __syncthreads();

    // block max of asrc (any valid shift works; lrelu monotone)
    float v = asrc;
    #pragma unroll
    for (int o = 16; o; o >>= 1) v = fmaxf(v, __shfl_xor_sync(0xffffffffu, v, o));
    if ((tid & 31) == 0) sRed[tid >> 5] = v;
    __syncthreads();
    float smax = sRed[0];
    #pragma unroll
    for (int w = 1; w < 16; ++w) smax = fmaxf(smax, sRed[w]);

    const int s  = tid >> 7;        // j-split 0..3
    const int iq = tid & 127;       // i-quad
    const int i0 = iq * 4;

    float c1[4], c2[4];
    #pragma unroll
    for (int ii = 0; ii < 4; ++ii) {
        const float4 xi = sX[i0 + ii];
        const float ad = xi.x * wdv.x + xi.y * wdv.y + xi.z * wdv.z + xi.w * wdv.w;
        const float aL = ad * L2E, aL2 = ad * C02;
        const float Mlog = fmaxf(aL + smax * L2E, aL2 + smax * C02);
        c1[ii] = aL - Mlog;
        c2[ii] = aL2 - Mlog;
    }

    float ssum[4] = {0.f, 0.f, 0.f, 0.f};
    float ax[4] = {0.f, 0.f, 0.f, 0.f};
    float ay[4] = {0.f, 0.f, 0.f, 0.f};
    float az[4] = {0.f, 0.f, 0.f, 0.f};
    float aw[4] = {0.f, 0.f, 0.f, 0.f};

    const float* ap = adj + (size_t)bt * NN * NN + i0;
    const int jbeg = s * 128;

    #pragma unroll 1
    for (int j = jbeg; j < jbeg + 128; j += 4) {
        const float4 A0 = __ldg((const float4*)(ap + (size_t)(j + 0) * NN));
        const float4 A1 = __ldg((const float4*)(ap + (size_t)(j + 1) * NN));
        const float4 A2 = __ldg((const float4*)(ap + (size_t)(j + 2) * NN));
        const float4 A3 = __ldg((const float4*)(ap + (size_t)(j + 3) * NN));
        #pragma unroll
        for (int u = 0; u < 4; ++u) {
            const float4 a = (u == 0) ? A0 : (u == 1) ? A1 : (u == 2) ? A2 : A3;
            const float2 sj = sS2[j + u];
            const float4 xj = sX[j + u];
            const float am[4] = {a.x, a.y, a.z, a.w};
            #pragma unroll
            for (int ii = 0; ii < 4; ++ii) {
                const float e = fmaxf(c1[ii] + sj.x, c2[ii] + sj.y);
                float p = ex2f(e);
                p = (am[ii] != 0.f) ? p : 0.f;
                ssum[ii] += p;
                ax[ii] += p * xj.x; ay[ii] += p * xj.y;
                az[ii] += p * xj.z; aw[ii] += p * xj.w;
            }
        }
    }

    // diagonal fixup: my split contains my quad's diagonal iff (iq>>5)==s
    if ((iq >> 5) == s) {
        #pragma unroll
        for (int ii = 0; ii < 4; ++ii) {
            const int i = i0 + ii;
            const float aii = __ldg(ap + (size_t)i * NN + ii);
            if (aii == 0.f) {
                const float2 sj = sS2[i];
                const float p = ex2f(fmaxf(c1[ii] + sj.x, c2[ii] + sj.y));
                const float4 xi = sX[i];
                ssum[ii] += p;
                ax[ii] += p * xi.x; ay[ii] += p * xi.y;
                az[ii] += p * xi.z; aw[ii] += p * xi.w;
            }
        }
    }

    float* pp = sPart + (size_t)(s * 128 + iq) * 20;
    #pragma unroll
    for (int ii = 0; ii < 4; ++ii) {
        pp[ii * 5 + 0] = ax[ii]; pp[ii * 5 + 1] = ay[ii];
        pp[ii * 5 + 2] = az[ii]; pp[ii * 5 + 3] = aw[ii];
        pp[ii * 5 + 4] = ssum[ii];
    }
    __syncthreads();

    // final reduce over splits: thread tid owns target i = tid
    const int q2 = tid >> 2, i2 = tid & 3;
    float vx = 0.f, vy = 0.f, vz = 0.f, vw = 0.f, sv = 0.f;
    #pragma unroll
    for (int s2 = 0; s2 < 4; ++s2) {
        const float* p2 = sPart + (size_t)(s2 * 128 + q2) * 20 + i2 * 5;
        vx += p2[0]; vy += p2[1]; vz += p2[2]; vw += p2[3]; sv += p2[4];
    }
    const size_t o = (size_t)bt * NN + tid;
    float4 av; av.x = vx; av.y = vy; av.z = vz; av.w = vw;
    g_acc[o] = av;
    g_inv[o] = 1.f / sv;
}

// ---------------------------------------------------------------------------
// Kernel 2: GRU gates (folded through C, d computed in-kernel) + recurrence.
//   b = m>>9, t' = (m>>6)&7, n' = (m&63)*8 + t  (raw .view faithfulness)
// All 8 timesteps prefetched (contiguous 128B per thread).
// ---------------------------------------------------------------------------
__global__ void __launch_bounds__(128)
gru_rec_kernel(const float* __restrict__ gatW, const float* __restrict__ Wih,
               const float* __restrict__ bih, const float* __restrict__ gbias,
               const float* __restrict__ Whh, const float* __restrict__ bhh)
{
    __shared__ float sC[48], sd[12], sWhh[48], sbhh[12];
    const int tid = threadIdx.x;
    if (tid < 48) {
        const int f = tid / 12, k = tid % 12;
        float sacc = 0.f;
        for (int h = 0; h < NH; ++h) sacc += gatW[f * NH + h] * Wih[k * NH + h];
        sC[f * 12 + k] = sacc;
        sWhh[tid] = Whh[tid];
    }
    if (tid < 12) {
        float sacc = bih[tid];
        for (int h = 0; h < NH; ++h) sacc += Wih[tid * NH + h] * gbias[h];
        sd[tid] = sacc;
        sbhh[tid] = bhh[tid];
    }
    __syncthreads();

    const int m = blockIdx.x * 128 + tid;
    const int base = ((m >> 9) * 8 + ((m >> 6) & 7)) * NN + (m & 63) * 8;

    float4 A[8];
    #pragma unroll
    for (int t = 0; t < NT; ++t) A[t] = g_acc[base + t];
    float inv[8];
    {
        const float4 I0 = *(const float4*)(g_inv + base);
        const float4 I1 = *(const float4*)(g_inv + base + 4);
        inv[0] = I0.x; inv[1] = I0.y; inv[2] = I0.z; inv[3] = I0.w;
        inv[4] = I1.x; inv[5] = I1.y; inv[6] = I1.z; inv[7] = I1.w;
    }

    float h[4] = {0.f, 0.f, 0.f, 0.f};
    float4* op = (float4*)(g_gru + (size_t)m * (NT * NF));

    #pragma unroll
    for (int t = 0; t < NT; ++t) {
        const float4 a = A[t];
        const float iv = inv[t];
        float gx[12];
        #pragma unroll
        for (int k = 0; k < 12; ++k)
            gx[k] = iv * (a.x * sC[k] + a.y * sC[12 + k] + a.z * sC[24 + k] + a.w * sC[36 + k]) + sd[k];

        float hn[4];
        #pragma unroll
        for (int c = 0; c < 4; ++c) {
            float ghr = sbhh[c]     + h[0]*sWhh[c*4]     + h[1]*sWhh[c*4+1]     + h[2]*sWhh[c*4+2]     + h[3]*sWhh[c*4+3];
            float ghz = sbhh[4 + c] + h[0]*sWhh[(4+c)*4] + h[1]*sWhh[(4+c)*4+1] + h[2]*sWhh[(4+c)*4+2] + h[3]*sWhh[(4+c)*4+3];
            float ghn = sbhh[8 + c] + h[0]*sWhh[(8+c)*4] + h[1]*sWhh[(8+c)*4+1] + h[2]*sWhh[(8+c)*4+2] + h[3]*sWhh[(8+c)*4+3];
            float r  = sigmf(gx[c] + ghr);
            float z  = sigmf(gx[4 + c] + ghz);
            float nc = tanhfast(gx[8 + c] + r * ghn);
            hn[c] = (1.f - z) * nc + z * h[c];
        }
        #pragma unroll
        for (int c = 0; c < 4; ++c) h[c] = hn[c];
        float4 hv; hv.x = h[0]; hv.y = h[1]; hv.z = h[2]; hv.w = h[3];
        op[t] = hv;
    }
}

// ---------------------------------------------------------------------------
// Kernel 3: Conv2d(8->12, 3x3 SAME over [N,4]) + Linear(4->2).
// Block = 256 threads = (64 n) x (4 co-splits of 3). Grid = 32 b x 8 ngroups.
// smem tile 66 rows x 8 float4 (pad-9 stride => conflict-free LDS.128).
// ---------------------------------------------------------------------------
__global__ void __launch_bounds__(256)
conv_kernel(const float* __restrict__ cW, const float* __restrict__ cB,
            const float* __restrict__ oW, const float* __restrict__ oB,
            float* __restrict__ out)
{
    __shared__ float4 sG[66 * 9];
    __shared__ float4 sW4[288];          // [(ci*3+kh)*12 + co] = {w0,w1,w2,0}
    __shared__ float sCB[12], sOW[8], sOB[2];

    const int tid = threadIdx.x;
    const int b   = blockIdx.x >> 3;
    const int n0  = (blockIdx.x & 7) * 64;

    for (int k = tid; k < 288; k += 256) {
        const int co = k % 12, r = k / 12, kh = r % 3, ci = r / 3;
        const float* wp = cW + (((size_t)co * NT + ci) * 3 + kh) * 3;
        float4 w; w.x = wp[0]; w.y = wp[1]; w.z = wp[2]; w.w = 0.f;
        sW4[(ci * 3 + kh) * 12 + co] = w;
    }
    if (tid < 12) sCB[tid] = cB[tid];
    if (tid < 8)  sOW[tid] = oW[tid];
    if (tid < 2)  sOB[tid] = oB[tid];

    const float4* gp = (const float4*)(g_gru + (size_t)b * NN * 32);
    for (int k = tid; k < 528; k += 256) {
        const int row = k >> 3, q = k & 7;
        const int nn = n0 + row - 1;
        float4 val = {0.f, 0.f, 0.f, 0.f};
        if (nn >= 0 && nn < NN) val = gp[nn * 8 + q];
        sG[row * 9 + q] = val;
    }
    __syncthreads();

    const int nloc = tid & 63;
    const int cos  = tid >> 6;           // 0..3 -> co = cos*3 + cc

    float y[3][4];
    #pragma unroll
    for (int cc = 0; cc < 3; ++cc) {
        const float cb = sCB[cos * 3 + cc];
        y[cc][0] = cb; y[cc][1] = cb; y[cc][2] = cb; y[cc][3] = cb;
    }

    #pragma unroll
    for (int ci = 0; ci < NT; ++ci) {
        #pragma unroll
        for (int kh = 0; kh < 3; ++kh) {
            const float4 vv = sG[(nloc + kh) * 9 + ci];
            #pragma unroll
            for (int cc = 0; cc < 3; ++cc) {
                const float4 w4 = sW4[(ci * 3 + kh) * 12 + cos * 3 + cc];
                y[cc][0] += vv.x * w4.y + vv.y * w4.z;
                y[cc][1] += vv.x * w4.x + vv.y * w4.y + vv.z * w4.z;
                y[cc][2] += vv.y * w4.x + vv.z * w4.y + vv.w * w4.z;
                y[cc][3] += vv.z * w4.x + vv.w * w4.y;
            }
        }
    }

    const int n = n0 + nloc;
    float* op = out + (((size_t)b * NCO + cos * 3) * NN + n) * 2;
    #pragma unroll
    for (int cc = 0; cc < 3; ++cc) {
        float2 o;
        o.x = sOB[0] + y[cc][0]*sOW[0] + y[cc][1]*sOW[1] + y[cc][2]*sOW[2] + y[cc][3]*sOW[3];
        o.y = sOB[1] + y[cc][0]*sOW[4] + y[cc][1]*sOW[5] + y[cc][2]*sOW[6] + y[cc][3]*sOW[7];
        *(float2*)(op + (size_t)cc * (NN * 2)) = o;
    }
}

// ---------------------------------------------------------------------------
extern "C" void kernel_launch(void* const* d_in, const int* in_sizes, int n_in,
                              void* d_out, int out_size)
{
    const float* x        = (const float*)d_in[0];
    const float* adj      = (const float*)d_in[1];
    const float* gat_W    = (const float*)d_in[2];
    const float* att_src  = (const float*)d_in[3];
    const float* att_dst  = (const float*)d_in[4];
    const float* gat_bias = (const float*)d_in[5];
    const float* gru_Wih  = (const float*)d_in[6];
    const float* gru_Whh  = (const float*)d_in[7];
    const float* gru_bih  = (const float*)d_in[8];
    const float* gru_bhh  = (const float*)d_in[9];
    const float* conv_W   = (const float*)d_in[10];
    const float* conv_b   = (const float*)d_in[11];
    const float* out_W    = (const float*)d_in[12];
    const float* out_b    = (const float*)d_in[13];
    float* out = (float*)d_out;

    const int gat_smem = 8192 + 4096 + 64 + 32 + 4 * 128 * 20 * 4;   // 53344 B
    cudaFuncSetAttribute(gat_kernel, cudaFuncAttributeMaxDynamicSharedMemorySize, gat_smem);

    gat_kernel<<<NB * NT, 512, gat_smem>>>(x, adj, gat_W, att_src, att_dst);
    gru_rec_kernel<<<(NB * NN) / 128, 128>>>(gat_W, gru_Wih, gru_bih, gat_bias, gru_Whh, gru_bhh);
    conv_kernel<<<NB * 8, 256>>>(conv_W, conv_b, out_W, out_b, out);
}